// round 2
// baseline (speedup 1.0000x reference)
#include <cuda_runtime.h>
#include <cuda_bf16.h>
#include <math.h>

// Problem constants (fixed by the dataset): B=128, S=1024, d=64, D=64.
#define S_LEN  1024
#define D_DIM  64
#define NSYM   64
#define DEPTH  4          // register prefetch ring depth (issue distance = 3 steps)

// Transposed bf16 core: coreT[s][j][i] = bf16(core[s][i][j]).  512 KB static.
__device__ __nv_bfloat16 g_coreT[NSYM * D_DIM * D_DIM];

__global__ void ttrain_prep_kernel(const float* __restrict__ core) {
    int idx = blockIdx.x * blockDim.x + threadIdx.x;
    if (idx < NSYM * D_DIM * D_DIM) {
        int s   = idx >> 12;        // / 4096
        int rem = idx & 4095;
        int i   = rem >> 6;         // row of core[s]
        int j   = rem & 63;         // col of core[s]  (coalesced read over j)
        g_coreT[(s << 12) + (j << 6) + i] = __float2bfloat16(core[idx]);
    }
}

// One CTA per batch element. 128 threads.
// warp w (0..3) owns outputs j in [16w, 16w+16); lane l: j = 16w + (l>>1), p = l&1.
// Thread (j,p) accumulates sum over i in [32p, 32p+32); pair-combined via shfl_xor(1).
// Weight slice per thread: coreT[s] + j*64 + p*32  ->  64 contiguous bytes (4x LDG.128),
// and across a warp the 32 lanes cover 2048 contiguous bytes (fully coalesced).
__global__ __launch_bounds__(128, 1) void ttrain_main_kernel(
    const int*   __restrict__ X,
    const float* __restrict__ lb,
    const float* __restrict__ rb,
    float*       __restrict__ out)
{
    __shared__ __align__(16) float s_c[2][D_DIM];   // double-buffered c vector
    __shared__ float s_red[4];
    __shared__ int   sX[S_LEN];

    const int tid = threadIdx.x;
    const int b   = blockIdx.x;
    const int w   = tid >> 5;
    const int l   = tid & 31;
    const int j   = (w << 4) + (l >> 1);
    const int p   = l & 1;

    // Stage this batch's symbol sequence and the initial c = left_boundary.
    const int* Xb = X + b * S_LEN;
    for (int k = tid; k < S_LEN; k += 128) sX[k] = Xb[k];
    if (tid < D_DIM) s_c[0][tid] = lb[tid];
    __syncthreads();

    // Per-thread weight-slice offset within a symbol's 8192-byte matrix, in uint4 units.
    const uint4* wbase = reinterpret_cast<const uint4*>(g_coreT);
    const int    toff  = (w << 7) + (l << 2);     // (w*2048 + l*64) / 16

    uint4 wbuf[DEPTH][4];   // ring of prefetched weight slices (32 bf16 each)

#define LOAD_STAGE(dst, tstep) {                                   \
        const uint4* pw_ = wbase + (sX[(tstep)] << 9) + toff;      \
        (dst)[0] = pw_[0]; (dst)[1] = pw_[1];                      \
        (dst)[2] = pw_[2]; (dst)[3] = pw_[3]; }

    LOAD_STAGE(wbuf[0], 0)
    LOAD_STAGE(wbuf[1], 1)
    LOAD_STAGE(wbuf[2], 2)

    int e_total = 0;   // accumulated power-of-two renormalization exponent

    for (int t0 = 0; t0 < S_LEN; t0 += DEPTH) {
#pragma unroll
        for (int u = 0; u < DEPTH; ++u) {
            const int t  = t0 + u;
            const int pf = t + (DEPTH - 1);
            if (pf < S_LEN) {
                LOAD_STAGE(wbuf[(u + DEPTH - 1) % DEPTH], pf)
            }

            // c_out[j] partial = sum_{i in p-range} c[i] * w[i][j]
            const float4* cv4 =
                reinterpret_cast<const float4*>(&s_c[t & 1][p << 5]);
            const unsigned int* wd =
                reinterpret_cast<const unsigned int*>(wbuf[u]);

            float a0 = 0.f, a1 = 0.f, a2 = 0.f, a3 = 0.f;
#pragma unroll
            for (int q = 0; q < 8; ++q) {
                float4 cv = cv4[q];                    // broadcast LDS
                unsigned int w0 = wd[2 * q];           // bf16 pair (i=4q, 4q+1)
                unsigned int w1 = wd[2 * q + 1];       // bf16 pair (i=4q+2, 4q+3)
                a0 = fmaf(cv.x, __int_as_float(w0 << 16),          a0);
                a1 = fmaf(cv.y, __int_as_float(w0 & 0xffff0000u),  a1);
                a2 = fmaf(cv.z, __int_as_float(w1 << 16),          a2);
                a3 = fmaf(cv.w, __int_as_float(w1 & 0xffff0000u),  a3);
            }
            float part = (a0 + a1) + (a2 + a3);
            float cnew = part + __shfl_xor_sync(0xffffffffu, part, 1);

            // Exact power-of-two renormalization every 8 steps (cancels in the
            // final formula; keeps c comfortably inside fp32 range).
            if ((t & 7) == 7) {
                float m = fabsf(cnew);
#pragma unroll
                for (int o = 16; o >= 1; o >>= 1)
                    m = fmaxf(m, __shfl_xor_sync(0xffffffffu, m, o));
                if (l == 0) s_red[w] = m;
                __syncthreads();
                float bm = fmaxf(fmaxf(s_red[0], s_red[1]),
                                 fmaxf(s_red[2], s_red[3]));
                int e = ((__float_as_int(bm) >> 23) & 0xff) - 127;
                e_total += e;
                cnew *= __int_as_float((127 - e) << 23);   // exact 2^-e
            }

            if (p == 0) s_c[(t + 1) & 1][j] = cnew;
            __syncthreads();
        }
    }

    // Final contraction with the right boundary + log-likelihood.
    {
        float v = (p == 0) ? s_c[0][j] * rb[j] : 0.f;
#pragma unroll
        for (int o = 16; o >= 1; o >>= 1)
            v += __shfl_xor_sync(0xffffffffu, v, o);
        if (l == 0) s_red[w] = v;
        __syncthreads();
        if (tid == 0) {
            double ov = (double)s_red[0] + (double)s_red[1] +
                        (double)s_red[2] + (double)s_red[3];
            double lp = 2.0 * ((double)e_total * 0.6931471805599453 +
                               log(fabs(ov)));
            out[b] = (float)lp;
        }
    }
#undef LOAD_STAGE
}

extern "C" void kernel_launch(void* const* d_in, const int* in_sizes, int n_in,
                              void* d_out, int out_size) {
    // metadata order: X [128*1024] i32, core [64*64*64] f32,
    //                 left_boundary [64] f32, right_boundary [64] f32
    const int*   X    = (const int*)  d_in[0];
    const float* core = (const float*)d_in[1];
    const float* lb   = (const float*)d_in[2];
    const float* rb   = (const float*)d_in[3];
    float*       out  = (float*)d_out;

    ttrain_prep_kernel<<<(NSYM * D_DIM * D_DIM + 255) / 256, 256>>>(core);
    ttrain_main_kernel<<<128, 128>>>(X, lb, rb, out);
}

// round 3
// speedup vs baseline: 1.5875x; 1.5875x over previous
#include <cuda_runtime.h>
#include <cuda_bf16.h>
#include <math.h>

// Problem constants (fixed by the dataset): B=128, S=1024, d=64, D=64.
#define S_LEN   1024
#define D_DIM   64
#define NSYM    64
#define DEPTH   4      // register prefetch ring (issue distance = 3 steps)
#define HSTRIDE 80     // floats between the p0 and p1 partial arrays (bank skew 16)

// Transposed bf16 core: coreT[s][j][i] = bf16(core[s][i][j]).  512 KB static.
__device__ __nv_bfloat16 g_coreT[NSYM * D_DIM * D_DIM];

__global__ void ttrain_prep_kernel(const float* __restrict__ core) {
    int idx = blockIdx.x * blockDim.x + threadIdx.x;
    if (idx < NSYM * D_DIM * D_DIM) {
        int s   = idx >> 12;
        int rem = idx & 4095;
        int i   = rem >> 6;
        int j   = rem & 63;
        g_coreT[(s << 12) + (j << 6) + i] = __float2bfloat16(core[idx]);
    }
}

__device__ __forceinline__ unsigned long long fadd2(unsigned long long a,
                                                    unsigned long long b) {
    unsigned long long d;
    asm("add.rn.f32x2 %0, %1, %2;" : "=l"(d) : "l"(a), "l"(b));
    return d;
}
__device__ __forceinline__ unsigned long long ffma2(unsigned long long a,
                                                    unsigned long long b,
                                                    unsigned long long c) {
    unsigned long long d;
    asm("fma.rn.f32x2 %0, %1, %2, %3;" : "=l"(d) : "l"(a), "l"(b), "l"(c));
    return d;
}
// bf16 pair (packed in u32) -> packed f32x2 {lo=bf0, hi=bf1}
__device__ __forceinline__ unsigned long long bf2f2(unsigned int w) {
    unsigned long long d;
    asm("mov.b64 %0, {%1, %2};" : "=l"(d)
        : "r"(w << 16), "r"(w & 0xffff0000u));
    return d;
}

// One CTA per batch element, 128 threads.
// warp w (0..3) owns outputs j in [16w,16w+16); lane l: j = 16w + (l>>1), p = l&1.
// Thread (j,p): partial over i in [32p, 32p+32); BOTH partials stored to smem,
// combined by the consumer next step (no shfl on the critical path).
// Renormalization: every step, exact power-of-two scale from exponent of c[0]
// (uniform broadcast value; cancels exactly in the final log formula).
__global__ __launch_bounds__(128, 1) void ttrain_main_kernel(
    const int*   __restrict__ X,
    const float* __restrict__ lb,
    const float* __restrict__ rb,
    float*       __restrict__ out)
{
    __shared__ __align__(16) float s_p[2][2][HSTRIDE];  // [buf][i-half][padded 64]
    __shared__ float s_red[4];
    __shared__ int   sX[S_LEN];

    const int tid = threadIdx.x;
    const int b   = blockIdx.x;
    const int w   = tid >> 5;
    const int l   = tid & 31;
    const int j   = (w << 4) + (l >> 1);
    const int p   = l & 1;

    const int* Xb = X + b * S_LEN;
    for (int k = tid; k < S_LEN; k += 128) sX[k] = Xb[k];
    if (tid < D_DIM) {                       // initial c = left_boundary
        int o = tid + ((tid >> 5) << 2);     // pad: +4 floats per 32 (bank skew)
        s_p[0][0][o] = lb[tid];
        s_p[0][1][o] = 0.f;
    }
    __syncthreads();

    // Per-thread weight slice: coreT[s] + j*64 + p*32 bf16 = 64 contiguous bytes.
    const uint4* wbase = reinterpret_cast<const uint4*>(g_coreT);
    const int    toff  = (j << 3) + (p << 2);

    uint4 ring[DEPTH][4];
#define LOADW(dst, tt) {                                                  \
        const uint4* pw_ = wbase + (sX[(tt) & (S_LEN - 1)] << 9) + toff;  \
        (dst)[0] = pw_[0]; (dst)[1] = pw_[1];                             \
        (dst)[2] = pw_[2]; (dst)[3] = pw_[3]; }

    LOADW(ring[0], 0)
    LOADW(ring[1], 1)
    LOADW(ring[2], 2)

    const int ibase = p ? 36 : 0;            // padded float offset of my i-half
    const int jo    = j + ((j >> 5) << 2);   // padded output offset

    int e_total = 0;

    for (int t0 = 0; t0 < S_LEN; t0 += DEPTH) {
#pragma unroll
        for (int u = 0; u < DEPTH; ++u) {
            const int t = t0 + u;
            LOADW(ring[(u + DEPTH - 1) % DEPTH], t + DEPTH - 1)

            const int    buf = t & 1;
            const float* P0  = s_p[buf][0];
            const float* P1  = s_p[buf][1];

            // Uniform power-of-two renorm scale from c[0] (broadcast; exact).
            float c0 = P0[0] + P1[0];
            int   e  = ((__float_as_int(c0) >> 23) & 0xff) - 127;
            e = e < -126 ? -126 : (e > 126 ? 126 : e);
            e_total += e;
            const float scale = __int_as_float((127 - e) << 23);

            const ulonglong2* Av =
                reinterpret_cast<const ulonglong2*>(P0 + ibase);
            const ulonglong2* Bv =
                reinterpret_cast<const ulonglong2*>(P1 + ibase);
            const unsigned int* wd =
                reinterpret_cast<const unsigned int*>(ring[u]);

            unsigned long long acc0 = 0ull, acc1 = 0ull;  // packed {+0,+0}
#pragma unroll
            for (int q = 0; q < 8; ++q) {
                ulonglong2 av = Av[q], bv = Bv[q];
                unsigned long long cA = fadd2(av.x, bv.x);  // {c[4q],c[4q+1]}
                unsigned long long cB = fadd2(av.y, bv.y);  // {c[4q+2],c[4q+3]}
                acc0 = ffma2(cA, bf2f2(wd[2 * q]),     acc0);
                acc1 = ffma2(cB, bf2f2(wd[2 * q + 1]), acc1);
            }
            float2 f0 = *reinterpret_cast<float2*>(&acc0);
            float2 f1 = *reinterpret_cast<float2*>(&acc1);
            float  tot = ((f0.x + f0.y) + (f1.x + f1.y)) * scale;

            s_p[buf ^ 1][p][jo] = tot;      // store MY partial; no shfl
            __syncthreads();
        }
    }
#undef LOADW

    // Final contraction with right boundary + log-likelihood.
    float v = 0.f;
    if (tid < D_DIM) {
        int o = tid + ((tid >> 5) << 2);
        v = (s_p[0][0][o] + s_p[0][1][o]) * rb[tid];
    }
#pragma unroll
    for (int o = 16; o >= 1; o >>= 1)
        v += __shfl_xor_sync(0xffffffffu, v, o);
    if (l == 0) s_red[w] = v;
    __syncthreads();
    if (tid == 0) {
        double ov = (double)s_red[0] + (double)s_red[1] +
                    (double)s_red[2] + (double)s_red[3];
        out[b] = (float)(2.0 * ((double)e_total * 0.6931471805599453 +
                                log(fabs(ov))));
    }
}

extern "C" void kernel_launch(void* const* d_in, const int* in_sizes, int n_in,
                              void* d_out, int out_size) {
    // metadata order: X [128*1024] i32, core [64*64*64] f32,
    //                 left_boundary [64] f32, right_boundary [64] f32
    const int*   X    = (const int*)  d_in[0];
    const float* core = (const float*)d_in[1];
    const float* lb   = (const float*)d_in[2];
    const float* rb   = (const float*)d_in[3];
    float*       out  = (float*)d_out;

    ttrain_prep_kernel<<<(NSYM * D_DIM * D_DIM + 255) / 256, 256>>>(core);
    ttrain_main_kernel<<<128, 128>>>(X, lb, rb, out);
}